// round 6
// baseline (speedup 1.0000x reference)
#include <cuda_runtime.h>

#define NB    50000
#define DIM   51
#define DD    2601
#define BATCH 8192

// block map: MIX region interleaves chain (g%5==0, 4096 blocks, 2 samples each)
// with bmv (16384 blocks, 2 samples each); then 64 small blocks.
#define CHAIN_BLOCKS 4096
#define BMV_BLOCKS   16384
#define MIX_BLOCKS   (CHAIN_BLOCKS + BMV_BLOCKS)   // 20480
#define SMALL_BLOCKS 64
#define TOTAL_BLOCKS (MIX_BLOCKS + SMALL_BLOCKS)   // 20544

// per-sub shared layout (floats): R matrix rows stride 53 (conflict-free),
// then es / cvec / dvec vectors. Chain reuses the same buffer with stride 52.
#define SUB_STRIDE 2880          // 16B-aligned (2880*4 = 11520)
#define OFF_ES     2703
#define OFF_CV     2755
#define OFF_DV     2807

__device__ float g_part[TOTAL_BLOCKS];
__device__ float g_sink;

// ---- packed f32x2 helpers (sm_100+ FFMA2) ---------------------------------
__device__ __forceinline__ unsigned long long pack2(float lo, float hi) {
    unsigned long long r;
    asm("mov.b64 %0, {%1, %2};" : "=l"(r) : "f"(lo), "f"(hi));
    return r;
}
__device__ __forceinline__ void unpack2(unsigned long long v, float &lo, float &hi) {
    asm("mov.b64 {%0, %1}, %2;" : "=f"(lo), "=f"(hi) : "l"(v));
}
__device__ __forceinline__ void ffma2(unsigned long long &d,
                                      unsigned long long a, unsigned long long b) {
    asm("fma.rn.f32x2 %0, %1, %2, %3;" : "=l"(d) : "l"(a), "l"(b), "l"(d));
}

__global__ void nop_kernel() {
    if (blockIdx.x == 0xFFFFFFFFu) g_sink = 1.f;   // never taken; keeps node non-empty
}

// ===========================================================================
__global__ void __launch_bounds__(128) fused_kernel(
    const int* __restrict__ nf1,  const int* __restrict__ nf2,
    const int* __restrict__ nf3,  const int* __restrict__ nf4,
    const int* __restrict__ top,  const int* __restrict__ nf3n,
    const int* __restrict__ nfc,  const int* __restrict__ radius,
    const float* __restrict__ cls, const float* __restrict__ rel)
{
    __shared__ __align__(16) float sbuf[2][SUB_STRIDE];
    __shared__ float redA[4], redB[4], redC[4];   // per (sub,warp) partials
    __shared__ float pcs[2], pds[2], subloss[2];

    const int g   = blockIdx.x;
    const int tid = threadIdx.x;

    if (g < MIX_BLOCKS && (g % 5) == 0) {
        // ------------------------- CHAIN ----------------------------------
        const int cid = g / 5;
        const int sub = tid >> 6;
        const int j   = tid & 63;
        const int s   = cid * 2 + sub;
        const int i0 = nfc[3 * s], i1 = nfc[3 * s + 1], i2 = nfc[3 * s + 2];

        float* cs = sbuf[sub];
        {
            const float* __restrict__ C = rel + (long)i0 * DD;
            for (int t = j; t < DD; t += 64) {
                const int r = t / 51;
                cs[r * 52 + (t - r * 51)] = C[t];
            }
            if (j < DIM) cs[j * 52 + 51] = 0.f;
        }

        unsigned long long dpk[26];
        if (j < DIM) {
            const float* __restrict__ Dm = rel + (long)i1 * DD;
            #pragma unroll
            for (int p = 0; p < 25; p++)
                dpk[p] = pack2(Dm[(2 * p) * DIM + j], Dm[(2 * p + 1) * DIM + j]);
            dpk[25] = pack2(Dm[50 * DIM + j], 0.f);
        }
        __syncthreads();

        float local = 0.f;
        if (j < DIM) {
            const float* __restrict__ E = rel + (long)i2 * DD;
            #pragma unroll 1
            for (int i = 0; i < DIM; i++) {
                const ulonglong2* __restrict__ crow = (const ulonglong2*)(cs + i * 52);
                unsigned long long q0 = 0ull, q1 = 0ull, q2 = 0ull, q3 = 0ull;
                #pragma unroll
                for (int m = 0; m < 13; m++) {
                    const ulonglong2 v = crow[m];
                    if (m & 1) { ffma2(q2, v.x, dpk[2 * m]); ffma2(q3, v.y, dpk[2 * m + 1]); }
                    else       { ffma2(q0, v.x, dpk[2 * m]); ffma2(q1, v.y, dpk[2 * m + 1]); }
                }
                float l0, h0, l1, h1, l2, h2, l3, h3;
                unpack2(q0, l0, h0); unpack2(q1, l1, h1);
                unpack2(q2, l2, h2); unpack2(q3, l3, h3);
                const float acc = ((l0 + h0) + (l1 + h1)) + ((l2 + h2) + (l3 + h3));
                local += fabsf(E[i * DIM + j] - acc);
            }
        }
        #pragma unroll
        for (int o = 16; o; o >>= 1)
            local += __shfl_xor_sync(0xffffffffu, local, o);
        if ((tid & 31) == 0) redA[tid >> 5] = local;
        __syncthreads();
        if (tid == 0)
            g_part[g] = (redA[0] + redA[1] + redA[2] + redA[3]) * (1.0f / (float)DD);

    } else if (g < MIX_BLOCKS) {
        // -------------------------- BMV -----------------------------------
        // 2 samples / block, 64 threads each. Matrix staged coalesced into
        // smem (stride 53 -> conflict-free row reads). Thread t owns row t.
        const int bid = g - g / 5 - 1;             // 0..16383
        const int sub = tid >> 6;
        const int t   = tid & 63;
        const int w   = bid * 2 + sub;             // 0..32767
        const int mode = w >> 13;
        const int s    = w & (BATCH - 1);

        const int* __restrict__ idx =
            (mode == 0) ? nf1 : (mode == 1) ? nf3 : (mode == 2) ? nf4 : nf3n;
        int ic, ir, id_;
        if (mode == 2) { ir = idx[3 * s]; ic = idx[3 * s + 1]; id_ = idx[3 * s + 2]; }
        else           { ic = idx[3 * s]; ir = idx[3 * s + 1]; id_ = idx[3 * s + 2]; }

        float* sb = sbuf[sub];
        float creg = 0.f, dreg = 0.f;
        if (t < DIM) {
            creg = cls[(long)ic * DIM + t];
            dreg = cls[(long)id_ * DIM + t];
            sb[OFF_CV + t] = creg;
            sb[OFF_DV + t] = dreg;
            sb[OFF_ES + t] = dreg - creg;
        }
        // stage R coalesced
        {
            const float* __restrict__ rm = rel + (long)ir * DD;
            #pragma unroll 4
            for (int q = t; q < DD; q += 64) {
                const int r = q / 51;
                sb[r * 53 + (q - r * 51)] = rm[q];
            }
        }
        __syncthreads();

        // dots
        float y = 0.f, pcd = 0.f;
        if (t < DIM) {
            const float* __restrict__ row = sb + t * 53;
            const float* __restrict__ ev  = sb + OFF_ES;
            float a0 = 0.f, a1 = 0.f, a2 = 0.f, a3 = 0.f;
            #pragma unroll
            for (int k = 0; k < 48; k += 4) {
                a0 = fmaf(row[k    ], ev[k    ], a0);
                a1 = fmaf(row[k + 1], ev[k + 1], a1);
                a2 = fmaf(row[k + 2], ev[k + 2], a2);
                a3 = fmaf(row[k + 3], ev[k + 3], a3);
            }
            a0 = fmaf(row[48], ev[48], a0);
            a1 = fmaf(row[49], ev[49], a1);
            a2 = fmaf(row[50], ev[50], a2);
            y = (a0 + a1) + (a2 + a3);
        } else if (t < 53) {
            // t==51: pc = row50 . c ; t==52: pd = row50 . d   (mode 0 only)
            const float* __restrict__ row = sb + 50 * 53;
            const float* __restrict__ v   = sb + ((t == 51) ? OFF_CV : OFF_DV);
            float a0 = 0.f, a1 = 0.f, a2 = 0.f;
            #pragma unroll
            for (int k = 0; k < 51; k += 3) {
                a0 = fmaf(row[k], v[k], a0);
                if (k + 1 < 51) a1 = fmaf(row[k + 1], v[k + 1], a1);
                if (k + 2 < 51) a2 = fmaf(row[k + 2], v[k + 2], a2);
            }
            pcd = a0 + a1 + a2;
        }
        if (t == 51) pcs[sub] = pcd;
        if (t == 52) pds[sub] = pcd;

        const bool in50 = (t < 50);
        float sc = in50 ? creg * creg : 0.f;
        float sd = in50 ? dreg * dreg : 0.f;
        float e2 = in50 ? y * y : 0.f;
        #pragma unroll
        for (int o = 16; o; o >>= 1) {
            sc += __shfl_xor_sync(0xffffffffu, sc, o);
            sd += __shfl_xor_sync(0xffffffffu, sd, o);
            e2 += __shfl_xor_sync(0xffffffffu, e2, o);
        }
        if ((tid & 31) == 0) {
            redA[tid >> 5] = sc; redB[tid >> 5] = sd; redC[tid >> 5] = e2;
        }
        __syncthreads();

        if (t == 0) {
            const int w0 = sub * 2;
            const float scf = redA[w0] + redA[w0 + 1];
            const float sdf = redB[w0] + redB[w0 + 1];
            const float euc = sqrtf(redC[w0] + redC[w0 + 1]);
            const float reg_c = fabsf(sqrtf(scf) - 1.0f);
            const float reg_d = fabsf(sqrtf(sdf) - 1.0f);
            float core;
            if (mode == 0) {
                core = fmaxf(euc + fmaxf(pcs[sub], 0.f) - fmaxf(pds[sub], 0.f), 0.f);
            } else {
                const float rc = fmaxf(sb[OFF_CV + 50], 0.f);
                const float rd = fmaxf(sb[OFF_DV + 50], 0.f);
                if (mode == 1)      core = fmaxf(euc + rc - rd, 0.f);
                else if (mode == 2) core = fmaxf(euc - rc - rd, 0.f);
                else                core = rc + rd - euc;
            }
            subloss[sub] = core + reg_c + reg_d;
        }
        __syncthreads();
        if (tid == 0) g_part[g] = subloss[0] + subloss[1];

    } else {
        // ------------------------- SMALL (nf2 + top - radius) -------------
        const int s = (g - MIX_BLOCKS) * 128 + tid;
        const float* __restrict__ c = cls + (long)nf2[3 * s]     * DIM;
        const float* __restrict__ d = cls + (long)nf2[3 * s + 1] * DIM;
        const float* __restrict__ e = cls + (long)nf2[3 * s + 2] * DIM;

        float s12 = 0.f, s13 = 0.f, s23 = 0.f, n1 = 0.f, n2 = 0.f, n3 = 0.f;
        #pragma unroll 5
        for (int k = 0; k < DIM - 1; k++) {
            const float x1 = c[k], x2 = d[k], x3 = e[k];
            const float d12 = x2 - x1, d13 = x3 - x1, d23 = x3 - x2;
            s12 = fmaf(d12, d12, s12);
            s13 = fmaf(d13, d13, s13);
            s23 = fmaf(d23, d23, s23);
            n1  = fmaf(x1, x1, n1);
            n2  = fmaf(x2, x2, n2);
            n3  = fmaf(x3, x3, n3);
        }
        const float rc = fmaxf(c[DIM - 1], 0.f);
        const float rd = fmaxf(d[DIM - 1], 0.f);
        const float re = fmaxf(e[DIM - 1], 0.f);
        float v = fmaxf(sqrtf(s12) - (rc + rd), 0.f)
                + fmaxf(sqrtf(s13) - rc, 0.f)
                + fmaxf(sqrtf(s23) - rd, 0.f)
                + fmaxf(fminf(rc, rd) - re, 0.f)
                + fabsf(sqrtf(n1) - 1.f)
                + fabsf(sqrtf(n2) - 1.f)
                + fabsf(sqrtf(n3) - 1.f);

        v += fabsf(fmaxf(cls[(long)top[s] * DIM + (DIM - 1)], 0.f) - 5.0f);
        v -= fminf(0.f, cls[(long)radius[s] * DIM + (DIM - 1)]);

        #pragma unroll
        for (int o = 16; o; o >>= 1)
            v += __shfl_xor_sync(0xffffffffu, v, o);
        if ((tid & 31) == 0) redA[tid >> 5] = v;
        __syncthreads();
        if (tid == 0)
            g_part[g] = (redA[0] + redA[1]) + (redA[2] + redA[3]);
    }
}

// ---------------------------------------------------------------------------
__global__ void __launch_bounds__(1024) finish_kernel(float* __restrict__ out)
{
    float t = 0.f;
    for (int i = threadIdx.x; i < TOTAL_BLOCKS; i += 1024) t += g_part[i];
    #pragma unroll
    for (int o = 16; o; o >>= 1)
        t += __shfl_xor_sync(0xffffffffu, t, o);
    __shared__ float ws[32];
    if ((threadIdx.x & 31) == 0) ws[threadIdx.x >> 5] = t;
    __syncthreads();
    if (threadIdx.x < 32) {
        float v = ws[threadIdx.x];
        #pragma unroll
        for (int o = 16; o; o >>= 1)
            v += __shfl_xor_sync(0xffffffffu, v, o);
        if (threadIdx.x == 0) out[0] = v * (1.0f / (float)BATCH);
    }
}

// ---------------------------------------------------------------------------
// Inputs: 0 nf1 1 nf2 2 nf3 3 nf4 4 top 5 nf3_neg 6 nf_inclusion(unused)
//         7 nf_chain 8 radius 9 cls_emb 10 rel_emb
// Launch cadence is 4 nodes so ncu (-s 5 -c 1) lands on fused_kernel.
// ---------------------------------------------------------------------------
extern "C" void kernel_launch(void* const* d_in, const int* in_sizes, int n_in,
                              void* d_out, int out_size)
{
    const int*   nf1    = (const int*)d_in[0];
    const int*   nf2    = (const int*)d_in[1];
    const int*   nf3    = (const int*)d_in[2];
    const int*   nf4    = (const int*)d_in[3];
    const int*   top    = (const int*)d_in[4];
    const int*   nf3n   = (const int*)d_in[5];
    const int*   nfc    = (const int*)d_in[7];
    const int*   radius = (const int*)d_in[8];
    const float* cls    = (const float*)d_in[9];
    const float* rel    = (const float*)d_in[10];
    float*       out    = (float*)d_out;

    nop_kernel<<<1, 32>>>();
    fused_kernel<<<TOTAL_BLOCKS, 128>>>(nf1, nf2, nf3, nf4, top, nf3n,
                                        nfc, radius, cls, rel);
    finish_kernel<<<1, 1024>>>(out);
    nop_kernel<<<1, 32>>>();
}

// round 7
// speedup vs baseline: 1.4050x; 1.4050x over previous
#include <cuda_runtime.h>

#define NB    50000
#define DIM   51
#define DD    2601
#define BATCH 8192

// MIX region: even g -> chain block (1 sample), odd g -> bmv block (4 warp-samples)
#define CHAIN_BLOCKS 8192
#define BMV_BLOCKS   8192
#define MIX_BLOCKS   (CHAIN_BLOCKS + BMV_BLOCKS)   // 16384
#define SMALL_BLOCKS 64
#define TOTAL_BLOCKS (MIX_BLOCKS + SMALL_BLOCKS)   // 16448

// partial-sum layout: chain per-block, bmv per-WARP, small per-block
#define PART_CHAIN 0
#define PART_BMV   8192
#define PART_SMALL (PART_BMV + 4 * BMV_BLOCKS)     // 40960
#define PART_TOTAL (PART_SMALL + SMALL_BLOCKS)     // 41024

__device__ float g_part[PART_TOTAL];
__device__ float g_sink;

// ---- packed f32x2 helpers (sm_100+) ---------------------------------------
__device__ __forceinline__ unsigned long long pack2(float lo, float hi) {
    unsigned long long r;
    asm("mov.b64 %0, {%1, %2};" : "=l"(r) : "f"(lo), "f"(hi));
    return r;
}
__device__ __forceinline__ void unpack2(unsigned long long v, float &lo, float &hi) {
    asm("mov.b64 {%0, %1}, %2;" : "=f"(lo), "=f"(hi) : "l"(v));
}
__device__ __forceinline__ void ffma2(unsigned long long &d,
                                      unsigned long long a, unsigned long long b) {
    asm("fma.rn.f32x2 %0, %1, %2, %3;" : "=l"(d) : "l"(a), "l"(b), "l"(d));
}

__global__ void nop_kernel() {
    if (blockIdx.x == 0xFFFFFFFFu) g_sink = 1.f;
}

// ===========================================================================
__global__ void __launch_bounds__(128) fused_kernel(
    const int* __restrict__ nf1,  const int* __restrict__ nf2,
    const int* __restrict__ nf3,  const int* __restrict__ nf4,
    const int* __restrict__ top,  const int* __restrict__ nf3n,
    const int* __restrict__ nfc,  const int* __restrict__ radius,
    const float* __restrict__ cls, const float* __restrict__ rel)
{
    __shared__ __align__(16) float cs[DIM * 52];   // 10608 B (chain only)
    __shared__ float red[4];

    const int g   = blockIdx.x;
    const int tid = threadIdx.x;

    if (g < MIX_BLOCKS && (g & 1) == 0) {
        // ------------------------- CHAIN (1 sample / block) ---------------
        // thread j = tid&63 owns output column j (j<51); half = tid>>6 owns
        // 26 rows (half0: 0..25 with row25 weighted 0; half1: 25..50).
        const int s    = g >> 1;
        const int half = tid >> 6;
        const int j    = tid & 63;
        const int i0 = nfc[3 * s], i1 = nfc[3 * s + 1], i2 = nfc[3 * s + 2];

        {
            const float* __restrict__ C = rel + (long)i0 * DD;
            #pragma unroll 3
            for (int t = tid; t < DD; t += 128) {
                const int r = t / 51;
                cs[r * 52 + (t - r * 51)] = C[t];
            }
            if (tid < DIM) cs[tid * 52 + 51] = 0.f;   // zero pad column
        }

        unsigned long long dpk[26];
        if (j < DIM) {
            const float* __restrict__ Dm = rel + (long)i1 * DD;
            #pragma unroll
            for (int p = 0; p < 25; p++)
                dpk[p] = pack2(Dm[(2 * p) * DIM + j], Dm[(2 * p + 1) * DIM + j]);
            dpk[25] = pack2(Dm[50 * DIM + j], 0.f);
        }
        __syncthreads();

        float local = 0.f;
        if (j < DIM) {
            const float* __restrict__ Erow = rel + (long)i2 * DD + half * 25 * DIM + j;
            const float* __restrict__ csbase = cs + half * 25 * 52;

            float er[4];
            #pragma unroll
            for (int u = 0; u < 4; u++) er[u] = Erow[u * DIM];

            #pragma unroll
            for (int u = 0; u < 26; u++) {
                const ulonglong2* __restrict__ crow =
                    (const ulonglong2*)(csbase + u * 52);
                unsigned long long q0 = 0ull, q1 = 0ull, q2 = 0ull, q3 = 0ull;
                #pragma unroll
                for (int m = 0; m < 13; m++) {
                    const ulonglong2 v = crow[m];
                    if (m & 1) { ffma2(q2, v.x, dpk[2 * m]); ffma2(q3, v.y, dpk[2 * m + 1]); }
                    else       { ffma2(q0, v.x, dpk[2 * m]); ffma2(q1, v.y, dpk[2 * m + 1]); }
                }
                const float ecur = er[u & 3];
                if (u + 4 < 26) er[u & 3] = Erow[(u + 4) * DIM];

                float l0, h0, l1, h1, l2, h2, l3, h3;
                unpack2(q0, l0, h0); unpack2(q1, l1, h1);
                unpack2(q2, l2, h2); unpack2(q3, l3, h3);
                const float acc = ((l0 + h0) + (l1 + h1)) + ((l2 + h2) + (l3 + h3));
                const float t = fabsf(ecur - acc);
                local += (u == 25) ? ((half == 0) ? 0.f : t) : t;
            }
        }
        #pragma unroll
        for (int o = 16; o; o >>= 1)
            local += __shfl_xor_sync(0xffffffffu, local, o);
        if ((tid & 31) == 0) red[tid >> 5] = local;
        __syncthreads();
        if (tid == 0)
            g_part[PART_CHAIN + s] =
                (red[0] + red[1] + red[2] + red[3]) * (1.0f / (float)DD);

    } else if (g < MIX_BLOCKS) {
        // -------------------------- BMV (warp / sample) --------------------
        // y = R(d-c), euclidean over rows 0..49. Distance-2 pipelined row
        // groups (5 rows each). Fully warp-local: no smem, no syncthreads.
        const int bid  = g >> 1;
        const int wl   = tid >> 5;
        const int lane = tid & 31;
        const int w    = bid * 4 + wl;          // 0..32767
        const int mode = w >> 13;
        const int s    = w & (BATCH - 1);

        const int* __restrict__ idx =
            (mode == 0) ? nf1 : (mode == 1) ? nf3 : (mode == 2) ? nf4 : nf3n;
        int ic, ir, id_;
        if (mode == 2) { ir = idx[3 * s]; ic = idx[3 * s + 1]; id_ = idx[3 * s + 2]; }
        else           { ic = idx[3 * s]; ir = idx[3 * s + 1]; id_ = idx[3 * s + 2]; }

        const float* __restrict__ rm = rel + (long)ir * DD;
        const bool hi = (lane < DIM - 32);      // lanes 0..18

        // front-batch: groups 0,1 of the matrix + c/d + row50 (~26 loads in flight)
        float xa[5], xb[5], na[5], nb[5];
        #pragma unroll
        for (int u = 0; u < 5; u++) {
            const float* __restrict__ row = rm + u * DIM;
            xa[u] = row[lane];
            xb[u] = hi ? row[lane + 32] : 0.f;
        }
        #pragma unroll
        for (int u = 0; u < 5; u++) {
            const float* __restrict__ row = rm + (5 + u) * DIM;
            na[u] = row[lane];
            nb[u] = hi ? row[lane + 32] : 0.f;
        }
        const float* __restrict__ cp = cls + (long)ic  * DIM;
        const float* __restrict__ dp = cls + (long)id_ * DIM;
        const float c0 = cp[lane];
        const float d0 = dp[lane];
        const float c1 = hi ? cp[lane + 32] : 0.f;
        const float d1 = hi ? dp[lane + 32] : 0.f;
        const float* __restrict__ r50 = rm + 50 * DIM;
        const float r50a = r50[lane];
        const float r50b = hi ? r50[lane + 32] : 0.f;

        const float e0 = d0 - c0;
        const float e1 = d1 - c1;

        // regularizer sums (exclude element 50 = lane18-hi)
        float sc = c0 * c0 + ((lane < 18) ? c1 * c1 : 0.f);
        float sd = d0 * d0 + ((lane < 18) ? d1 * d1 : 0.f);
        #pragma unroll
        for (int o = 16; o; o >>= 1) {
            sc += __shfl_xor_sync(0xffffffffu, sc, o);
            sd += __shfl_xor_sync(0xffffffffu, sd, o);
        }
        const float c_last = __shfl_sync(0xffffffffu, c1, 18);
        const float d_last = __shfl_sync(0xffffffffu, d1, 18);

        float euc2 = 0.f;
        #pragma unroll
        for (int gr = 0; gr < 10; gr++) {
            float p[5];
            if ((gr & 1) == 0) {
                #pragma unroll
                for (int u = 0; u < 5; u++) p[u] = xa[u] * e0 + xb[u] * e1;
                if (gr + 2 < 10) {
                    #pragma unroll
                    for (int u = 0; u < 5; u++) {
                        const float* __restrict__ row = rm + ((gr + 2) * 5 + u) * DIM;
                        xa[u] = row[lane];
                        xb[u] = hi ? row[lane + 32] : 0.f;
                    }
                }
            } else {
                #pragma unroll
                for (int u = 0; u < 5; u++) p[u] = na[u] * e0 + nb[u] * e1;
                if (gr + 2 < 10) {
                    #pragma unroll
                    for (int u = 0; u < 5; u++) {
                        const float* __restrict__ row = rm + ((gr + 2) * 5 + u) * DIM;
                        na[u] = row[lane];
                        nb[u] = hi ? row[lane + 32] : 0.f;
                    }
                }
            }
            #pragma unroll
            for (int o = 16; o; o >>= 1) {
                #pragma unroll
                for (int u = 0; u < 5; u++)
                    p[u] += __shfl_xor_sync(0xffffffffu, p[u], o);
            }
            #pragma unroll
            for (int u = 0; u < 5; u++)
                euc2 = fmaf(p[u], p[u], euc2);
        }
        const float euc = sqrtf(euc2);

        float core;
        if (mode == 0) {
            float pc = r50a * c0 + r50b * c1;
            float pd = r50a * d0 + r50b * d1;
            #pragma unroll
            for (int o = 16; o; o >>= 1) {
                pc += __shfl_xor_sync(0xffffffffu, pc, o);
                pd += __shfl_xor_sync(0xffffffffu, pd, o);
            }
            core = fmaxf(euc + fmaxf(pc, 0.f) - fmaxf(pd, 0.f), 0.f);
        } else {
            const float rc = fmaxf(c_last, 0.f);
            const float rd = fmaxf(d_last, 0.f);
            if (mode == 1)      core = fmaxf(euc + rc - rd, 0.f);
            else if (mode == 2) core = fmaxf(euc - rc - rd, 0.f);
            else                core = rc + rd - euc;           // nf3_neg
        }
        if (lane == 0)
            g_part[PART_BMV + w] = core + fabsf(sqrtf(sc) - 1.0f)
                                        + fabsf(sqrtf(sd) - 1.0f);

    } else {
        // ------------------------- SMALL (nf2 + top - radius) -------------
        const int s = (g - MIX_BLOCKS) * 128 + tid;
        const float* __restrict__ c = cls + (long)nf2[3 * s]     * DIM;
        const float* __restrict__ d = cls + (long)nf2[3 * s + 1] * DIM;
        const float* __restrict__ e = cls + (long)nf2[3 * s + 2] * DIM;

        float s12 = 0.f, s13 = 0.f, s23 = 0.f, n1 = 0.f, n2 = 0.f, n3 = 0.f;
        #pragma unroll 5
        for (int k = 0; k < DIM - 1; k++) {
            const float x1 = c[k], x2 = d[k], x3 = e[k];
            const float d12 = x2 - x1, d13 = x3 - x1, d23 = x3 - x2;
            s12 = fmaf(d12, d12, s12);
            s13 = fmaf(d13, d13, s13);
            s23 = fmaf(d23, d23, s23);
            n1  = fmaf(x1, x1, n1);
            n2  = fmaf(x2, x2, n2);
            n3  = fmaf(x3, x3, n3);
        }
        const float rc = fmaxf(c[DIM - 1], 0.f);
        const float rd = fmaxf(d[DIM - 1], 0.f);
        const float re = fmaxf(e[DIM - 1], 0.f);
        float v = fmaxf(sqrtf(s12) - (rc + rd), 0.f)
                + fmaxf(sqrtf(s13) - rc, 0.f)
                + fmaxf(sqrtf(s23) - rd, 0.f)
                + fmaxf(fminf(rc, rd) - re, 0.f)
                + fabsf(sqrtf(n1) - 1.f)
                + fabsf(sqrtf(n2) - 1.f)
                + fabsf(sqrtf(n3) - 1.f);

        v += fabsf(fmaxf(cls[(long)top[s] * DIM + (DIM - 1)], 0.f) - 5.0f);
        v -= fminf(0.f, cls[(long)radius[s] * DIM + (DIM - 1)]);

        #pragma unroll
        for (int o = 16; o; o >>= 1)
            v += __shfl_xor_sync(0xffffffffu, v, o);
        if ((tid & 31) == 0) red[tid >> 5] = v;
        __syncthreads();
        if (tid == 0)
            g_part[PART_SMALL + (g - MIX_BLOCKS)] =
                (red[0] + red[1]) + (red[2] + red[3]);
    }
}

// ---------------------------------------------------------------------------
__global__ void __launch_bounds__(1024) finish_kernel(float* __restrict__ out)
{
    float t = 0.f;
    for (int i = threadIdx.x; i < PART_TOTAL; i += 1024) t += g_part[i];
    #pragma unroll
    for (int o = 16; o; o >>= 1)
        t += __shfl_xor_sync(0xffffffffu, t, o);
    __shared__ float ws[32];
    if ((threadIdx.x & 31) == 0) ws[threadIdx.x >> 5] = t;
    __syncthreads();
    if (threadIdx.x < 32) {
        float v = ws[threadIdx.x];
        #pragma unroll
        for (int o = 16; o; o >>= 1)
            v += __shfl_xor_sync(0xffffffffu, v, o);
        if (threadIdx.x == 0) out[0] = v * (1.0f / (float)BATCH);
    }
}

// ---------------------------------------------------------------------------
// Inputs: 0 nf1 1 nf2 2 nf3 3 nf4 4 top 5 nf3_neg 6 nf_inclusion(unused)
//         7 nf_chain 8 radius 9 cls_emb 10 rel_emb
// 3 launches/call so the profiled launch (#8) is fused_kernel.
// ---------------------------------------------------------------------------
extern "C" void kernel_launch(void* const* d_in, const int* in_sizes, int n_in,
                              void* d_out, int out_size)
{
    const int*   nf1    = (const int*)d_in[0];
    const int*   nf2    = (const int*)d_in[1];
    const int*   nf3    = (const int*)d_in[2];
    const int*   nf4    = (const int*)d_in[3];
    const int*   top    = (const int*)d_in[4];
    const int*   nf3n   = (const int*)d_in[5];
    const int*   nfc    = (const int*)d_in[7];
    const int*   radius = (const int*)d_in[8];
    const float* cls    = (const float*)d_in[9];
    const float* rel    = (const float*)d_in[10];
    float*       out    = (float*)d_out;

    nop_kernel<<<1, 32>>>();
    fused_kernel<<<TOTAL_BLOCKS, 128>>>(nf1, nf2, nf3, nf4, top, nf3n,
                                        nfc, radius, cls, rel);
    finish_kernel<<<1, 1024>>>(out);
}

// round 8
// speedup vs baseline: 1.5172x; 1.0799x over previous
#include <cuda_runtime.h>

#define NB    50000
#define DIM   51
#define DD    2601
#define BATCH 8192

// MIX region: even g -> chain block (1 sample), odd g -> bmv block (4 warp-samples)
#define CHAIN_BLOCKS 8192
#define BMV_BLOCKS   8192
#define MIX_BLOCKS   (CHAIN_BLOCKS + BMV_BLOCKS)   // 16384
#define SMALL_BLOCKS 64
#define TOTAL_BLOCKS (MIX_BLOCKS + SMALL_BLOCKS)   // 16448

#define PART_CHAIN 0
#define PART_BMV   8192
#define PART_SMALL (PART_BMV + 4 * BMV_BLOCKS)     // 40960
#define PART_TOTAL (PART_SMALL + SMALL_BLOCKS)     // 41024

__device__ float g_part[PART_TOTAL];
__device__ float g_sink;

#define FULLMASK 0xffffffffu

// ---- packed f32x2 helpers (sm_100+) ---------------------------------------
__device__ __forceinline__ unsigned long long pack2(float lo, float hi) {
    unsigned long long r;
    asm("mov.b64 %0, {%1, %2};" : "=l"(r) : "f"(lo), "f"(hi));
    return r;
}
__device__ __forceinline__ void unpack2(unsigned long long v, float &lo, float &hi) {
    asm("mov.b64 {%0, %1}, %2;" : "=f"(lo), "=f"(hi) : "l"(v));
}
__device__ __forceinline__ void ffma2(unsigned long long &d,
                                      unsigned long long a, unsigned long long b) {
    asm("fma.rn.f32x2 %0, %1, %2, %3;" : "=l"(d) : "l"(a), "l"(b), "l"(d));
}

// Merge-reduce 4 values with 6 shfls. Afterward each lane holds the FULL sum
// of one value chosen by (bit16,bit8): (0,0)->p0 (0,1)->p2 (1,0)->p1 (1,1)->p3.
__device__ __forceinline__ float merge4(float p0, float p1, float p2, float p3,
                                        int lane)
{
    const bool b16 = (lane & 16) != 0;
    const bool b8  = (lane & 8)  != 0;
    float x1 = (b16 ? p1 : p0) + __shfl_xor_sync(FULLMASK, b16 ? p0 : p1, 16);
    float x2 = (b16 ? p3 : p2) + __shfl_xor_sync(FULLMASK, b16 ? p2 : p3, 16);
    float y  = (b8 ? x2 : x1)  + __shfl_xor_sync(FULLMASK, b8 ? x1 : x2, 8);
    y += __shfl_xor_sync(FULLMASK, y, 4);
    y += __shfl_xor_sync(FULLMASK, y, 2);
    y += __shfl_xor_sync(FULLMASK, y, 1);
    return y;
}

__global__ void nop_kernel() {
    if (blockIdx.x == 0xFFFFFFFFu) g_sink = 1.f;
}

// ===========================================================================
__global__ void __launch_bounds__(128) fused_kernel(
    const int* __restrict__ nf1,  const int* __restrict__ nf2,
    const int* __restrict__ nf3,  const int* __restrict__ nf4,
    const int* __restrict__ top,  const int* __restrict__ nf3n,
    const int* __restrict__ nfc,  const int* __restrict__ radius,
    const float* __restrict__ cls, const float* __restrict__ rel)
{
    __shared__ __align__(16) float cs[DIM * 52];   // 10608 B (chain only)
    __shared__ float red[4];

    const int g   = blockIdx.x;
    const int tid = threadIdx.x;

    if (g < MIX_BLOCKS && (g & 1) == 0) {
        // ------------------------- CHAIN (1 sample / block) ---------------
        const int s    = g >> 1;
        const int half = tid >> 6;
        const int j    = tid & 63;
        const int i0 = nfc[3 * s], i1 = nfc[3 * s + 1], i2 = nfc[3 * s + 2];

        {
            const float* __restrict__ C = rel + (long)i0 * DD;
            #pragma unroll 3
            for (int t = tid; t < DD; t += 128) {
                const int r = t / 51;
                cs[r * 52 + (t - r * 51)] = C[t];
            }
            if (tid < DIM) cs[tid * 52 + 51] = 0.f;
        }

        unsigned long long dpk[26];
        if (j < DIM) {
            const float* __restrict__ Dm = rel + (long)i1 * DD;
            #pragma unroll
            for (int p = 0; p < 25; p++)
                dpk[p] = pack2(Dm[(2 * p) * DIM + j], Dm[(2 * p + 1) * DIM + j]);
            dpk[25] = pack2(Dm[50 * DIM + j], 0.f);
        }
        __syncthreads();

        float local = 0.f;
        if (j < DIM) {
            const float* __restrict__ Erow = rel + (long)i2 * DD + half * 25 * DIM + j;
            const float* __restrict__ csbase = cs + half * 25 * 52;

            float er[4];
            #pragma unroll
            for (int u = 0; u < 4; u++) er[u] = Erow[u * DIM];

            #pragma unroll
            for (int u = 0; u < 26; u++) {
                const ulonglong2* __restrict__ crow =
                    (const ulonglong2*)(csbase + u * 52);
                unsigned long long q0 = 0ull, q1 = 0ull, q2 = 0ull, q3 = 0ull;
                #pragma unroll
                for (int m = 0; m < 13; m++) {
                    const ulonglong2 v = crow[m];
                    if (m & 1) { ffma2(q2, v.x, dpk[2 * m]); ffma2(q3, v.y, dpk[2 * m + 1]); }
                    else       { ffma2(q0, v.x, dpk[2 * m]); ffma2(q1, v.y, dpk[2 * m + 1]); }
                }
                const float ecur = er[u & 3];
                if (u + 4 < 26) er[u & 3] = Erow[(u + 4) * DIM];

                float l0, h0, l1, h1, l2, h2, l3, h3;
                unpack2(q0, l0, h0); unpack2(q1, l1, h1);
                unpack2(q2, l2, h2); unpack2(q3, l3, h3);
                const float acc = ((l0 + h0) + (l1 + h1)) + ((l2 + h2) + (l3 + h3));
                const float t = fabsf(ecur - acc);
                local += (u == 25) ? ((half == 0) ? 0.f : t) : t;
            }
        }
        #pragma unroll
        for (int o = 16; o; o >>= 1)
            local += __shfl_xor_sync(FULLMASK, local, o);
        if ((tid & 31) == 0) red[tid >> 5] = local;
        __syncthreads();
        if (tid == 0)
            g_part[PART_CHAIN + s] =
                (red[0] + red[1] + red[2] + red[3]) * (1.0f / (float)DD);

    } else if (g < MIX_BLOCKS) {
        // -------------------------- BMV (warp / sample) --------------------
        // 13 groups of 4 rows; merge-reduce (6 shfls/group) leaves each row
        // sum replicated in an 8-lane set; square locally, /8 at the end.
        const int bid  = g >> 1;
        const int wl   = tid >> 5;
        const int lane = tid & 31;
        const int w    = bid * 4 + wl;
        const int mode = w >> 13;
        const int s    = w & (BATCH - 1);

        const int* __restrict__ idx =
            (mode == 0) ? nf1 : (mode == 1) ? nf3 : (mode == 2) ? nf4 : nf3n;
        int ic, ir, id_;
        if (mode == 2) { ir = idx[3 * s]; ic = idx[3 * s + 1]; id_ = idx[3 * s + 2]; }
        else           { ic = idx[3 * s]; ir = idx[3 * s + 1]; id_ = idx[3 * s + 2]; }

        const float* __restrict__ rm = rel + (long)ir * DD;
        const bool hi = (lane < DIM - 32);      // lanes 0..18

        // front-batch groups 0,1 (+ c/d + row50): ~22 loads in flight
        float xa[4], xb[4], na[4], nb[4];
        #pragma unroll
        for (int u = 0; u < 4; u++) {
            const float* __restrict__ row = rm + u * DIM;
            xa[u] = row[lane];
            xb[u] = hi ? row[lane + 32] : 0.f;
        }
        #pragma unroll
        for (int u = 0; u < 4; u++) {
            const float* __restrict__ row = rm + (4 + u) * DIM;
            na[u] = row[lane];
            nb[u] = hi ? row[lane + 32] : 0.f;
        }
        const float* __restrict__ cp = cls + (long)ic  * DIM;
        const float* __restrict__ dp = cls + (long)id_ * DIM;
        const float c0 = cp[lane];
        const float d0 = dp[lane];
        const float c1 = hi ? cp[lane + 32] : 0.f;
        const float d1 = hi ? dp[lane + 32] : 0.f;
        const float* __restrict__ r50 = rm + 50 * DIM;
        const float r50a = r50[lane];
        const float r50b = hi ? r50[lane + 32] : 0.f;

        const float e0 = d0 - c0;
        const float e1 = d1 - c1;

        // regularizer sums via merge trick (exclude elem 50 = lane18-hi)
        const float scp = c0 * c0 + ((lane < 18) ? c1 * c1 : 0.f);
        const float sdp = d0 * d0 + ((lane < 18) ? d1 * d1 : 0.f);
        float scv;
        {
            const bool b16 = (lane & 16) != 0;
            float v = (b16 ? sdp : scp) +
                      __shfl_xor_sync(FULLMASK, b16 ? scp : sdp, 16);
            v += __shfl_xor_sync(FULLMASK, v, 8);
            v += __shfl_xor_sync(FULLMASK, v, 4);
            v += __shfl_xor_sync(FULLMASK, v, 2);
            v += __shfl_xor_sync(FULLMASK, v, 1);
            scv = v;   // lanes b16=0: sum(sc), b16=1: sum(sd)
        }
        const float sc_tot = __shfl_sync(FULLMASK, scv, 0);
        const float sd_tot = __shfl_sync(FULLMASK, scv, 16);
        const float c_last = __shfl_sync(FULLMASK, c1, 18);
        const float d_last = __shfl_sync(FULLMASK, d1, 18);

        // euclidean: rows 0..49 in 13 groups of 4 (group 12 has 2 dummies)
        float vsq = 0.f;
        #pragma unroll
        for (int gr = 0; gr < 13; gr++) {
            float p[4];
            float* A = ((gr & 1) == 0) ? xa : na;
            float* B = ((gr & 1) == 0) ? xb : nb;
            #pragma unroll
            for (int u = 0; u < 4; u++) {
                const bool valid = (4 * gr + u) < 50;
                p[u] = valid ? (A[u] * e0 + B[u] * e1) : 0.f;
            }
            if (gr + 2 < 13) {
                #pragma unroll
                for (int u = 0; u < 4; u++) {
                    const int r = (gr + 2) * 4 + u;
                    if (r < 50) {
                        const float* __restrict__ row = rm + r * DIM;
                        A[u] = row[lane];
                        B[u] = hi ? row[lane + 32] : 0.f;
                    }
                }
            }
            const float y = merge4(p[0], p[1], p[2], p[3], lane);
            vsq = fmaf(y, y, vsq);
        }
        // Σ_lanes vsq = 8 * euc2
        #pragma unroll
        for (int o = 16; o; o >>= 1)
            vsq += __shfl_xor_sync(FULLMASK, vsq, o);
        const float euc = sqrtf(vsq * 0.125f);

        float core;
        if (mode == 0) {
            const float pcp = r50a * c0 + r50b * c1;
            const float pdp = r50a * d0 + r50b * d1;
            const float yv = merge4(pcp, pdp, 0.f, 0.f, lane);
            const float pc = __shfl_sync(FULLMASK, yv, 0);    // (b16=0,b8=0)
            const float pd = __shfl_sync(FULLMASK, yv, 16);   // (b16=1,b8=0)
            core = fmaxf(euc + fmaxf(pc, 0.f) - fmaxf(pd, 0.f), 0.f);
        } else {
            const float rc = fmaxf(c_last, 0.f);
            const float rd = fmaxf(d_last, 0.f);
            if (mode == 1)      core = fmaxf(euc + rc - rd, 0.f);
            else if (mode == 2) core = fmaxf(euc - rc - rd, 0.f);
            else                core = rc + rd - euc;           // nf3_neg
        }
        if (lane == 0)
            g_part[PART_BMV + w] = core + fabsf(sqrtf(sc_tot) - 1.0f)
                                        + fabsf(sqrtf(sd_tot) - 1.0f);

    } else {
        // ------------------------- SMALL (nf2 + top - radius) -------------
        const int s = (g - MIX_BLOCKS) * 128 + tid;
        const float* __restrict__ c = cls + (long)nf2[3 * s]     * DIM;
        const float* __restrict__ d = cls + (long)nf2[3 * s + 1] * DIM;
        const float* __restrict__ e = cls + (long)nf2[3 * s + 2] * DIM;

        float s12 = 0.f, s13 = 0.f, s23 = 0.f, n1 = 0.f, n2 = 0.f, n3 = 0.f;
        #pragma unroll 5
        for (int k = 0; k < DIM - 1; k++) {
            const float x1 = c[k], x2 = d[k], x3 = e[k];
            const float d12 = x2 - x1, d13 = x3 - x1, d23 = x3 - x2;
            s12 = fmaf(d12, d12, s12);
            s13 = fmaf(d13, d13, s13);
            s23 = fmaf(d23, d23, s23);
            n1  = fmaf(x1, x1, n1);
            n2  = fmaf(x2, x2, n2);
            n3  = fmaf(x3, x3, n3);
        }
        const float rc = fmaxf(c[DIM - 1], 0.f);
        const float rd = fmaxf(d[DIM - 1], 0.f);
        const float re = fmaxf(e[DIM - 1], 0.f);
        float v = fmaxf(sqrtf(s12) - (rc + rd), 0.f)
                + fmaxf(sqrtf(s13) - rc, 0.f)
                + fmaxf(sqrtf(s23) - rd, 0.f)
                + fmaxf(fminf(rc, rd) - re, 0.f)
                + fabsf(sqrtf(n1) - 1.f)
                + fabsf(sqrtf(n2) - 1.f)
                + fabsf(sqrtf(n3) - 1.f);

        v += fabsf(fmaxf(cls[(long)top[s] * DIM + (DIM - 1)], 0.f) - 5.0f);
        v -= fminf(0.f, cls[(long)radius[s] * DIM + (DIM - 1)]);

        #pragma unroll
        for (int o = 16; o; o >>= 1)
            v += __shfl_xor_sync(FULLMASK, v, o);
        if ((tid & 31) == 0) red[tid >> 5] = v;
        __syncthreads();
        if (tid == 0)
            g_part[PART_SMALL + (g - MIX_BLOCKS)] =
                (red[0] + red[1]) + (red[2] + red[3]);
    }
}

// ---------------------------------------------------------------------------
__global__ void __launch_bounds__(1024) finish_kernel(float* __restrict__ out)
{
    float t = 0.f;
    for (int i = threadIdx.x; i < PART_TOTAL; i += 1024) t += g_part[i];
    #pragma unroll
    for (int o = 16; o; o >>= 1)
        t += __shfl_xor_sync(FULLMASK, t, o);
    __shared__ float ws[32];
    if ((threadIdx.x & 31) == 0) ws[threadIdx.x >> 5] = t;
    __syncthreads();
    if (threadIdx.x < 32) {
        float v = ws[threadIdx.x];
        #pragma unroll
        for (int o = 16; o; o >>= 1)
            v += __shfl_xor_sync(FULLMASK, v, o);
        if (threadIdx.x == 0) out[0] = v * (1.0f / (float)BATCH);
    }
}

// ---------------------------------------------------------------------------
// Inputs: 0 nf1 1 nf2 2 nf3 3 nf4 4 top 5 nf3_neg 6 nf_inclusion(unused)
//         7 nf_chain 8 radius 9 cls_emb 10 rel_emb
// Cycle [fused, finish, nop]: the profiled launch (global position 4) is
// fused_kernel.
// ---------------------------------------------------------------------------
extern "C" void kernel_launch(void* const* d_in, const int* in_sizes, int n_in,
                              void* d_out, int out_size)
{
    const int*   nf1    = (const int*)d_in[0];
    const int*   nf2    = (const int*)d_in[1];
    const int*   nf3    = (const int*)d_in[2];
    const int*   nf4    = (const int*)d_in[3];
    const int*   top    = (const int*)d_in[4];
    const int*   nf3n   = (const int*)d_in[5];
    const int*   nfc    = (const int*)d_in[7];
    const int*   radius = (const int*)d_in[8];
    const float* cls    = (const float*)d_in[9];
    const float* rel    = (const float*)d_in[10];
    float*       out    = (float*)d_out;

    fused_kernel<<<TOTAL_BLOCKS, 128>>>(nf1, nf2, nf3, nf4, top, nf3n,
                                        nfc, radius, cls, rel);
    finish_kernel<<<1, 1024>>>(out);
    nop_kernel<<<1, 32>>>();
}